// round 11
// baseline (speedup 1.0000x reference)
#include <cuda_runtime.h>
#include <cuda_bf16.h>
#include <math.h>
#include <stdint.h>

#define NR   8192
#define DIMK 512
#define DKC  128
#define DVC  128
#define NCH  256
#define CHS  32      // NCH*CHS == NR
#define NB   4096    // rank buckets
#define STR  132     // padded column stride (129 used: 128 v-cols + 1 weight col)

// ---------------- scratch (device globals; no allocation) ----------------
__device__ float          g_u1[DIMK], g_u2[DIMK];
__device__ float          g_d1, g_d2;
__device__ __nv_bfloat162 g_xh2[NR * DIMK / 2], g_xl2[NR * DIMK / 2];
__device__ __nv_bfloat16  g_wh[DVC * DIMK], g_wl[DVC * DIMK];
__device__ float          g_v[NR * DVC];
__device__ float          g_ssrc[NR];
__device__ float          g_t[NR];
__device__ unsigned       g_s[NR];          // sortable u32 of t
__device__ int            g_b[NR];          // bucket of t
__device__ unsigned       g_smin, g_smax;   // sortable min/max of t
__device__ int            g_hist[NB], g_bcnt[NB], g_cum[NB + 1];
__device__ unsigned       g_pkey[NR];       // bucket-grouped keys
__device__ int            g_pid[NR];        // bucket-grouped indices
__device__ int            g_idx[NR];        // sorted order -> original index
__device__ int            g_kq[NR];         // per-row threshold rank
__device__ float          g_pf[NR], g_qf[NR];  // per-row (p,q) mixing pair
__device__ float          g_w1[NR], g_w2[NR];
__device__ float          g_A1[NR * STR];   // per-chunk local exclusive prefix, w1*v
__device__ float          g_A2[NR * STR];   // per-chunk local exclusive prefix, w2*v
__device__ float          g_cT1[NCH * STR], g_cT2[NCH * STR];
__device__ float          g_S1f[(NCH + 1) * STR];  // suffix incl chunk (float)
__device__ float          g_P2f[(NCH + 1) * STR];  // prefix excl chunk (float)
__device__ volatile unsigned g_barA, g_barB;       // software grid barriers

__device__ __forceinline__ unsigned f2sort(float f) {
    unsigned u = __float_as_uint(f);
    return (u & 0x80000000u) ? ~u : (u | 0x80000000u);
}
__device__ __forceinline__ float sort2f(unsigned s) {
    unsigned u = (s & 0x80000000u) ? (s & 0x7FFFFFFFu) : ~s;
    return __uint_as_float(u);
}
__device__ __forceinline__ int bucket_of(float t, float tmin, float scale) {
    int b = (int)((t - tmin) * scale);
    if (b < 0) b = 0;
    if (b > NB - 1) b = NB - 1;
    return b;
}
__device__ __forceinline__ void grid_bar(volatile unsigned* ctr, unsigned target) {
    __syncthreads();
    if (threadIdx.x == 0) {
        __threadfence();
        atomicAdd((unsigned*)ctr, 1u);
        while (*ctr < target) { }
        __threadfence();
    }
    __syncthreads();
}
__device__ __forceinline__ void mma16816(float* c, const unsigned* a, const unsigned* b) {
    asm volatile(
        "mma.sync.aligned.m16n8k16.row.col.f32.bf16.bf16.f32 "
        "{%0,%1,%2,%3}, {%4,%5,%6,%7}, {%8,%9}, {%0,%1,%2,%3};\n"
        : "+f"(c[0]), "+f"(c[1]), "+f"(c[2]), "+f"(c[3])
        : "r"(a[0]), "r"(a[1]), "r"(a[2]), "r"(a[3]), "r"(b[0]), "r"(b[1]));
}
__device__ __forceinline__ void cpasync16(void* smem, const void* gmem) {
    unsigned sa = (unsigned)__cvta_generic_to_shared(smem);
    asm volatile("cp.async.cg.shared.global [%0], [%1], 16;\n" :: "r"(sa), "l"(gmem));
}

// ---------------- 0: clear + fold a into W + convert Wv ------------------
__global__ void __launch_bounds__(512) prep_k(const float* __restrict__ W,
                                              const float* __restrict__ b,
                                              const float* __restrict__ a,
                                              const float* __restrict__ Wv) {
    int gi = blockIdx.x * 512 + threadIdx.x;   // 0..16383
    if (gi < NB) { g_hist[gi] = 0; g_bcnt[gi] = 0; }
    if (gi == 0) { g_smin = 0xFFFFFFFFu; g_smax = 0u; g_barA = 0u; g_barB = 0u; }
    int e0 = gi * 4;
    #pragma unroll
    for (int j = 0; j < 4; j++) {
        float w = Wv[e0 + j];
        __nv_bfloat16 h = __float2bfloat16_rn(w);
        __nv_bfloat16 l = __float2bfloat16_rn(w - __bfloat162float(h));
        g_wh[e0 + j] = h;
        g_wl[e0 + j] = l;
    }
    if (blockIdx.x == 0) {
        int j = threadIdx.x;  // 0..511
        float u1 = 0.f, u2 = 0.f;
        #pragma unroll 8
        for (int k = 0; k < DKC; k++) {
            float w = W[k * DIMK + j];
            u1 += w * a[k];
            u2 += w * a[DKC + k];
        }
        g_u1[j] = u1;
        g_u2[j] = u2;
        if (j < 2) {
            float d = 0.f;
            const float* av = a + (j ? DKC : 0);
            for (int k = 0; k < DKC; k++) d += b[k] * av[k];
            if (j == 0) g_d1 = d; else g_d2 = d;
        }
    }
}

// ---- 1: s_src, t, sortable key, min/max + split-bf16 conversion of x ----
__global__ void __launch_bounds__(256) s_k(const float* __restrict__ x) {
    __shared__ unsigned wmin[8], wmax[8];
    int warp = threadIdx.x >> 5, lane = threadIdx.x & 31;
    int row = blockIdx.x * 8 + warp;
    const float4* xr = (const float4*)(x + row * DIMK);
    const float4* u1v = (const float4*)g_u1;
    const float4* u2v = (const float4*)g_u2;
    float a1 = 0.f, a2 = 0.f;
    #pragma unroll
    for (int m = lane; m < DIMK / 4; m += 32) {
        float4 xv = xr[m];
        float4 w1 = u1v[m];
        float4 w2 = u2v[m];
        a1 += xv.x * w1.x + xv.y * w1.y + xv.z * w1.z + xv.w * w1.w;
        a2 += xv.x * w2.x + xv.y * w2.y + xv.z * w2.z + xv.w * w2.w;
        __nv_bfloat162 h0 = __floats2bfloat162_rn(xv.x, xv.y);
        __nv_bfloat162 h1 = __floats2bfloat162_rn(xv.z, xv.w);
        __nv_bfloat162 l0 = __floats2bfloat162_rn(xv.x - __bfloat162float(h0.x),
                                                  xv.y - __bfloat162float(h0.y));
        __nv_bfloat162 l1 = __floats2bfloat162_rn(xv.z - __bfloat162float(h1.x),
                                                  xv.w - __bfloat162float(h1.y));
        long o = (long)row * (DIMK / 2) + m * 2;
        g_xh2[o] = h0; g_xh2[o + 1] = h1;
        g_xl2[o] = l0; g_xl2[o + 1] = l1;
    }
    #pragma unroll
    for (int off = 16; off > 0; off >>= 1) {
        a1 += __shfl_down_sync(0xffffffffu, a1, off);
        a2 += __shfl_down_sync(0xffffffffu, a2, off);
    }
    if (lane == 0) {
        float t = a2 + g_d2;
        g_ssrc[row] = a1 + g_d1;
        g_t[row] = t;
        unsigned s = f2sort(t);
        g_s[row] = s;
        wmin[warp] = s; wmax[warp] = s;
    }
    __syncthreads();
    if (threadIdx.x == 0) {
        unsigned mn = wmin[0], mx = wmax[0];
        #pragma unroll
        for (int w = 1; w < 8; w++) {
            mn = min(mn, wmin[w]);
            mx = max(mx, wmax[w]);
        }
        atomicMin(&g_smin, mn);
        atomicMax(&g_smax, mx);
    }
}

// ---- 2: fused bucket chain: hist + hscan + place + rank (64 blocks) -----
__global__ void __launch_bounds__(128) chain_k() {
    int tid = threadIdx.x;
    int i = blockIdx.x * 128 + tid;

    float tmin = sort2f(g_smin), tmax = sort2f(g_smax);
    float range = tmax - tmin;
    float scale = (range > 0.f) ? (float)(NB - 1) / range : 0.f;
    float T = tmax;

    // phase 1: histogram
    float t = g_t[i];
    unsigned si = g_s[i];
    int b = bucket_of(t, tmin, scale);
    g_b[i] = b;
    atomicAdd(&g_hist[b], 1);

    grid_bar(&g_barB, 64);

    // phase 2: block 0 scans the 4096-bucket histogram (128 thr x 32)
    if (blockIdx.x == 0) {
        __shared__ int wsum[4], wscan[4];
        int lane = tid & 31, w = tid >> 5;
        int v[32], loc[32], s = 0;
        #pragma unroll
        for (int q = 0; q < 8; q++) {
            int4 h = ((const int4*)g_hist)[tid * 8 + q];
            v[q * 4 + 0] = h.x; v[q * 4 + 1] = h.y;
            v[q * 4 + 2] = h.z; v[q * 4 + 3] = h.w;
        }
        #pragma unroll
        for (int e = 0; e < 32; e++) { loc[e] = s; s += v[e]; }
        int incl = s;
        #pragma unroll
        for (int off = 1; off < 32; off <<= 1) {
            int n = __shfl_up_sync(0xffffffffu, incl, off);
            if (lane >= off) incl += n;
        }
        if (lane == 31) wsum[w] = incl;
        __syncthreads();
        if (w == 0 && lane < 4) {
            int t2 = wsum[lane];
            int i2 = t2;
            #pragma unroll
            for (int off = 1; off < 4; off <<= 1) {
                int n = __shfl_up_sync(0x0000000fu, i2, off);
                if (lane >= off) i2 += n;
            }
            wscan[lane] = i2 - t2;
        }
        __syncthreads();
        int base = wscan[w] + incl - s;
        #pragma unroll
        for (int q = 0; q < 8; q++) {
            int4 o;
            o.x = base + loc[q * 4 + 0];
            o.y = base + loc[q * 4 + 1];
            o.z = base + loc[q * 4 + 2];
            o.w = base + loc[q * 4 + 3];
            ((int4*)g_cum)[tid * 8 + q] = o;
        }
        if (tid == 0) g_cum[NB] = NR;
    }

    grid_bar(&g_barB, 128);

    // phase 3: place
    int pos = g_cum[b] + atomicAdd(&g_bcnt[b], 1);
    g_pkey[pos] = si;
    g_pid[pos]  = i;

    grid_bar(&g_barB, 192);

    // phase 4: rank + threshold rank + weights + (p,q)
    {
        int lo = g_cum[b], hi = g_cum[b + 1];
        int r = lo;
        for (int p = lo; p < hi; p++) {
            unsigned sj = g_pkey[p];
            int ij = g_pid[p];
            r += (sj < si) || (sj == si && ij < i);
        }
        g_idx[r] = i;
        g_w1[r] = expf(t - T);
        g_w2[r] = expf(0.01f * (t - T));

        float c = g_ssrc[i];
        double gamma = exp(-0.99 * ((double)c + (double)T));
        if (gamma <= 1.0) { g_pf[i] = 1.f; g_qf[i] = (float)gamma; }
        else             { g_pf[i] = (float)(1.0 / gamma); g_qf[i] = 1.f; }

        float thr = -c;
        unsigned sthr = f2sort(thr);
        int bb = bucket_of(thr, tmin, scale);
        int kq = g_cum[bb];
        int hi2 = g_cum[bb + 1];
        for (int p = g_cum[bb]; p < hi2; p++) kq += (g_pkey[p] < sthr);
        g_kq[i] = kq;
    }
}

// ---- 3: v = x @ Wv^T + bv, mma.sync bf16 split, cp.async double-buffer --
#define ASTR 40   // bf16 row stride in smem (conflict-free)
#define TILE (64 * ASTR)
__global__ void __launch_bounds__(256) gemm_v_k(const float* __restrict__ bv) {
    __shared__ __nv_bfloat16 Ah[2 * TILE], Al[2 * TILE];
    __shared__ __nv_bfloat16 Bh[2 * TILE], Bl[2 * TILE];
    int tid = threadIdx.x;
    int wid = tid >> 5, lane = tid & 31;
    int warp_m = wid >> 1, warp_n = wid & 1;    // 4 x 2 warps
    int grp = lane >> 2, qid = lane & 3;
    int i0 = blockIdx.x * 64;
    int n0 = blockIdx.y * 64;

    const __nv_bfloat16* xh = (const __nv_bfloat16*)g_xh2;
    const __nv_bfloat16* xl = (const __nv_bfloat16*)g_xl2;

    int lrow = tid >> 2, lcol = (tid & 3) * 8;
    long aoff = (long)(i0 + lrow) * DIMK + lcol;
    long boff = (long)(n0 + lrow) * DIMK + lcol;
    int sidx = lrow * ASTR + lcol;

    float acc[4][4];
    #pragma unroll
    for (int nt = 0; nt < 4; nt++)
        #pragma unroll
        for (int q = 0; q < 4; q++) acc[nt][q] = 0.f;

    cpasync16(&Ah[sidx], &xh[aoff]);
    cpasync16(&Al[sidx], &xl[aoff]);
    cpasync16(&Bh[sidx], &g_wh[boff]);
    cpasync16(&Bl[sidx], &g_wl[boff]);
    asm volatile("cp.async.commit_group;\n");

    int buf = 0;
    for (int it = 0; it < DIMK / 32; it++) {
        if (it + 1 < DIMK / 32) {
            int nb = (buf ^ 1) * TILE;
            int k0 = (it + 1) * 32;
            cpasync16(&Ah[nb + sidx], &xh[aoff + k0]);
            cpasync16(&Al[nb + sidx], &xl[aoff + k0]);
            cpasync16(&Bh[nb + sidx], &g_wh[boff + k0]);
            cpasync16(&Bl[nb + sidx], &g_wl[boff + k0]);
            asm volatile("cp.async.commit_group;\n");
            asm volatile("cp.async.wait_group 1;\n");
        } else {
            asm volatile("cp.async.wait_group 0;\n");
        }
        __syncthreads();
        int cb = buf * TILE;
        #pragma unroll
        for (int kk = 0; kk < 32; kk += 16) {
            unsigned ah[4], al[4];
            int r0 = warp_m * 16 + grp;
            int cA = cb + kk + qid * 2;
            ah[0] = *(unsigned*)&Ah[r0 * ASTR + cA];
            ah[1] = *(unsigned*)&Ah[(r0 + 8) * ASTR + cA];
            ah[2] = *(unsigned*)&Ah[r0 * ASTR + cA + 8];
            ah[3] = *(unsigned*)&Ah[(r0 + 8) * ASTR + cA + 8];
            al[0] = *(unsigned*)&Al[r0 * ASTR + cA];
            al[1] = *(unsigned*)&Al[(r0 + 8) * ASTR + cA];
            al[2] = *(unsigned*)&Al[r0 * ASTR + cA + 8];
            al[3] = *(unsigned*)&Al[(r0 + 8) * ASTR + cA + 8];
            #pragma unroll
            for (int nt = 0; nt < 4; nt++) {
                int n = warp_n * 32 + nt * 8 + grp;
                unsigned bh[2], bl[2];
                bh[0] = *(unsigned*)&Bh[n * ASTR + cA];
                bh[1] = *(unsigned*)&Bh[n * ASTR + cA + 8];
                bl[0] = *(unsigned*)&Bl[n * ASTR + cA];
                bl[1] = *(unsigned*)&Bl[n * ASTR + cA + 8];
                mma16816(acc[nt], ah, bh);
                mma16816(acc[nt], ah, bl);
                mma16816(acc[nt], al, bh);
            }
        }
        __syncthreads();
        buf ^= 1;
    }
    #pragma unroll
    for (int nt = 0; nt < 4; nt++) {
        int col = n0 + warp_n * 32 + nt * 8 + qid * 2;
        float2 bb = *(const float2*)&bv[col];
        int row0 = i0 + warp_m * 16 + grp;
        float2 o0 = { acc[nt][0] + bb.x, acc[nt][1] + bb.y };
        float2 o1 = { acc[nt][2] + bb.x, acc[nt][3] + bb.y };
        *(float2*)&g_v[(long)row0 * DVC + col] = o0;
        *(float2*)&g_v[(long)(row0 + 8) * DVC + col] = o1;
    }
}

// ---- 4: fused tail: chunk prefixes + column scan + per-row combine ------
// grid = 256 blocks x 256 threads (2 blocks/SM -> single wave guaranteed)
__global__ void __launch_bounds__(256) tail_k(float* __restrict__ out) {
    __shared__ double s1[NCH], s2[NCH];
    int blk = blockIdx.x;   // 0..255
    int tid = threadIdx.x;  // 0..255

    // phase A: per-chunk local exclusive prefixes + chunk totals (chunk=blk)
    if (tid <= 128) {
        int d = tid;
        float a1 = 0.f, a2 = 0.f;
        int k0 = blk * CHS;
        #pragma unroll 4
        for (int e = 0; e < CHS; e++) {
            int k = k0 + e;
            float vv = (d < 128) ? g_v[g_idx[k] * DVC + d] : 1.0f;
            g_A1[k * STR + d] = a1;
            g_A2[k * STR + d] = a2;
            a1 = fmaf(g_w1[k], vv, a1);
            a2 = fmaf(g_w2[k], vv, a2);
        }
        g_cT1[blk * STR + d] = a1;
        g_cT2[blk * STR + d] = a2;
    }

    grid_bar(&g_barA, 256);

    // phase B: blocks 0..128 scan chunk totals for column d=blk
    if (blk < 129) {
        int d = blk, c = tid;
        double v1 = (double)g_cT1[c * STR + d], v2 = (double)g_cT2[c * STR + d];
        s1[c] = v1; s2[c] = v2;
        __syncthreads();
        for (int off = 1; off < NCH; off <<= 1) {
            double a = (c >= off) ? s1[c - off] : 0.0;
            double b = (c >= off) ? s2[c - off] : 0.0;
            __syncthreads();
            s1[c] += a; s2[c] += b;
            __syncthreads();
        }
        double tot1 = s1[NCH - 1], tot2 = s2[NCH - 1];
        g_S1f[c * STR + d] = (float)(tot1 - (s1[c] - v1));  // suffix incl chunk c
        g_P2f[c * STR + d] = (float)(s2[c] - v2);           // prefix excl chunk c
        if (c == 0) {
            g_S1f[NCH * STR + d] = 0.f;
            g_P2f[NCH * STR + d] = (float)tot2;
        }
    }

    grid_bar(&g_barA, 512);

    // phase C: per-row combine (32 rows per block; threads 0..127 = d)
    if (tid < 128) {
        int d = tid;
        int lane = d & 31;
        for (int rr = 0; rr < 32; rr++) {
            int i = blk * 32 + rr;
            int k = g_kq[i];
            float p = g_pf[i], q = g_qf[i];
            float suf, pre, sufZ, preZ;
            if (k < NR) {
                int ch = k / CHS;
                long cb = (long)ch * STR;
                long kb = (long)k * STR;
                suf  = g_S1f[cb + d]   - g_A1[kb + d];
                pre  = g_P2f[cb + d]   + g_A2[kb + d];
                sufZ = g_S1f[cb + 128] - g_A1[kb + 128];
                preZ = g_P2f[cb + 128] + g_A2[kb + 128];
            } else {
                long cb = (long)NCH * STR;
                suf = 0.f;  pre = g_P2f[cb + d];
                sufZ = 0.f; preZ = g_P2f[cb + 128];
            }
            float num = suf * p + pre * q;
            float den = sufZ * p + preZ * q;
            float inv;
            if (lane == 0) inv = 1.f / den;
            inv = __shfl_sync(0xffffffffu, inv, 0);
            out[i * DVC + d] = num * inv;
        }
    }
}

// ---------------- launch --------------------------------------------------
extern "C" void kernel_launch(void* const* d_in, const int* in_sizes, int n_in,
                              void* d_out, int out_size) {
    const float* x  = (const float*)d_in[0];
    const float* W  = (const float*)d_in[1];
    const float* b  = (const float*)d_in[2];
    const float* Wv = (const float*)d_in[3];
    const float* bv = (const float*)d_in[4];
    const float* a  = (const float*)d_in[5];
    float* out = (float*)d_out;

    static cudaStream_t s2 = nullptr;
    static cudaEvent_t evFork = nullptr, evJoin = nullptr;
    if (!s2) {
        cudaStreamCreateWithFlags(&s2, cudaStreamNonBlocking);
        cudaEventCreateWithFlags(&evFork, cudaEventDisableTiming);
        cudaEventCreateWithFlags(&evJoin, cudaEventDisableTiming);
    }

    prep_k<<<32, 512>>>(W, b, a, Wv);
    s_k<<<NR / 8, 256>>>(x);

    // fork: fused bucket/rank chain runs parallel to GEMM
    cudaEventRecord(evFork, 0);
    cudaStreamWaitEvent(s2, evFork, 0);
    chain_k<<<64, 128, 0, s2>>>();
    cudaEventRecord(evJoin, s2);

    dim3 ggrid(NR / 64, 2);
    gemm_v_k<<<ggrid, 256>>>(bv);

    // join
    cudaStreamWaitEvent(0, evJoin, 0);
    tail_k<<<256, 256>>>(out);
}

// round 13
// speedup vs baseline: 1.2826x; 1.2826x over previous
#include <cuda_runtime.h>
#include <cuda_bf16.h>
#include <math.h>
#include <stdint.h>

#define NR   8192
#define DIMK 512
#define DKC  128
#define DVC  128
#define NCH  256
#define CHS  32      // NCH*CHS == NR
#define NB   4096    // rank buckets
#define STR  132     // padded column stride (129 used: 128 v-cols + 1 weight col)

// ---------------- scratch (device globals; no allocation) ----------------
__device__ float          g_u1[DIMK], g_u2[DIMK];
__device__ float          g_d1, g_d2;
__device__ __nv_bfloat162 g_xh2[NR * DIMK / 2], g_xl2[NR * DIMK / 2];
__device__ __nv_bfloat16  g_wh[DVC * DIMK], g_wl[DVC * DIMK];
__device__ float          g_v[NR * DVC];
__device__ float          g_ssrc[NR];
__device__ float          g_t[NR];
__device__ unsigned       g_s[NR];          // sortable u32 of t
__device__ int            g_b[NR];          // bucket of t
__device__ unsigned       g_smin, g_smax;   // sortable min/max of t
__device__ int            g_hist[NB], g_bcnt[NB], g_cum[NB + 1];
__device__ unsigned       g_pkey[NR];       // bucket-grouped keys
__device__ int            g_pid[NR];        // bucket-grouped indices
__device__ int            g_idx[NR];        // sorted order -> original index
__device__ int            g_kq[NR];         // per-row threshold rank
__device__ float          g_pf[NR], g_qf[NR];  // per-row (p,q) mixing pair
__device__ float          g_w1[NR], g_w2[NR];
__device__ float          g_A1[NR * STR];   // per-chunk local exclusive prefix, w1*v
__device__ float          g_A2[NR * STR];   // per-chunk local exclusive prefix, w2*v
__device__ double         g_cT1[NCH * STR], g_cT2[NCH * STR];
__device__ float          g_S1f[(NCH + 1) * STR];  // suffix incl chunk (float)
__device__ float          g_P2f[(NCH + 1) * STR];  // prefix excl chunk (float)

__device__ __forceinline__ unsigned f2sort(float f) {
    unsigned u = __float_as_uint(f);
    return (u & 0x80000000u) ? ~u : (u | 0x80000000u);
}
__device__ __forceinline__ float sort2f(unsigned s) {
    unsigned u = (s & 0x80000000u) ? (s & 0x7FFFFFFFu) : ~s;
    return __uint_as_float(u);
}
__device__ __forceinline__ int bucket_of(float t, float tmin, float scale) {
    int b = (int)((t - tmin) * scale);
    if (b < 0) b = 0;
    if (b > NB - 1) b = NB - 1;
    return b;
}
__device__ __forceinline__ void mma16816(float* c, const unsigned* a, const unsigned* b) {
    asm volatile(
        "mma.sync.aligned.m16n8k16.row.col.f32.bf16.bf16.f32 "
        "{%0,%1,%2,%3}, {%4,%5,%6,%7}, {%8,%9}, {%0,%1,%2,%3};\n"
        : "+f"(c[0]), "+f"(c[1]), "+f"(c[2]), "+f"(c[3])
        : "r"(a[0]), "r"(a[1]), "r"(a[2]), "r"(a[3]), "r"(b[0]), "r"(b[1]));
}
__device__ __forceinline__ void cpasync16(void* smem, const void* gmem) {
    unsigned sa = (unsigned)__cvta_generic_to_shared(smem);
    asm volatile("cp.async.cg.shared.global [%0], [%1], 16;\n" :: "r"(sa), "l"(gmem));
}

// ---------------- 0: clear hist + fold a into W + convert Wv -------------
__global__ void __launch_bounds__(512) prep_k(const float* __restrict__ W,
                                              const float* __restrict__ b,
                                              const float* __restrict__ a,
                                              const float* __restrict__ Wv) {
    int gi = blockIdx.x * 512 + threadIdx.x;   // 0..16383
    if (gi < NB) { g_hist[gi] = 0; g_bcnt[gi] = 0; }
    if (gi == 0) { g_smin = 0xFFFFFFFFu; g_smax = 0u; }
    int e0 = gi * 4;
    #pragma unroll
    for (int j = 0; j < 4; j++) {
        float w = Wv[e0 + j];
        __nv_bfloat16 h = __float2bfloat16_rn(w);
        __nv_bfloat16 l = __float2bfloat16_rn(w - __bfloat162float(h));
        g_wh[e0 + j] = h;
        g_wl[e0 + j] = l;
    }
    if (blockIdx.x == 0) {
        int j = threadIdx.x;  // 0..511
        float u1 = 0.f, u2 = 0.f;
        #pragma unroll 8
        for (int k = 0; k < DKC; k++) {
            float w = W[k * DIMK + j];
            u1 += w * a[k];
            u2 += w * a[DKC + k];
        }
        g_u1[j] = u1;
        g_u2[j] = u2;
        if (j < 2) {
            float d = 0.f;
            const float* av = a + (j ? DKC : 0);
            for (int k = 0; k < DKC; k++) d += b[k] * av[k];
            if (j == 0) g_d1 = d; else g_d2 = d;
        }
    }
}

// ---- 1: s_src, t, sortable key, min/max + split-bf16 conversion of x ----
__global__ void __launch_bounds__(256) s_k(const float* __restrict__ x) {
    __shared__ unsigned wmin[8], wmax[8];
    int warp = threadIdx.x >> 5, lane = threadIdx.x & 31;
    int row = blockIdx.x * 8 + warp;
    const float4* xr = (const float4*)(x + row * DIMK);
    const float4* u1v = (const float4*)g_u1;
    const float4* u2v = (const float4*)g_u2;
    float a1 = 0.f, a2 = 0.f;
    #pragma unroll
    for (int m = lane; m < DIMK / 4; m += 32) {
        float4 xv = xr[m];
        float4 w1 = u1v[m];
        float4 w2 = u2v[m];
        a1 += xv.x * w1.x + xv.y * w1.y + xv.z * w1.z + xv.w * w1.w;
        a2 += xv.x * w2.x + xv.y * w2.y + xv.z * w2.z + xv.w * w2.w;
        __nv_bfloat162 h0 = __floats2bfloat162_rn(xv.x, xv.y);
        __nv_bfloat162 h1 = __floats2bfloat162_rn(xv.z, xv.w);
        __nv_bfloat162 l0 = __floats2bfloat162_rn(xv.x - __bfloat162float(h0.x),
                                                  xv.y - __bfloat162float(h0.y));
        __nv_bfloat162 l1 = __floats2bfloat162_rn(xv.z - __bfloat162float(h1.x),
                                                  xv.w - __bfloat162float(h1.y));
        long o = (long)row * (DIMK / 2) + m * 2;
        g_xh2[o] = h0; g_xh2[o + 1] = h1;
        g_xl2[o] = l0; g_xl2[o + 1] = l1;
    }
    #pragma unroll
    for (int off = 16; off > 0; off >>= 1) {
        a1 += __shfl_down_sync(0xffffffffu, a1, off);
        a2 += __shfl_down_sync(0xffffffffu, a2, off);
    }
    if (lane == 0) {
        float t = a2 + g_d2;
        g_ssrc[row] = a1 + g_d1;
        g_t[row] = t;
        unsigned s = f2sort(t);
        g_s[row] = s;
        wmin[warp] = s; wmax[warp] = s;
    }
    __syncthreads();
    if (threadIdx.x == 0) {
        unsigned mn = wmin[0], mx = wmax[0];
        #pragma unroll
        for (int w = 1; w < 8; w++) {
            mn = min(mn, wmin[w]);
            mx = max(mx, wmax[w]);
        }
        atomicMin(&g_smin, mn);
        atomicMax(&g_smax, mx);
    }
}

// ---- 2a: histogram of buckets -------------------------------------------
__global__ void __launch_bounds__(128) hist_k() {
    int i = blockIdx.x * 128 + threadIdx.x;
    float tmin = sort2f(g_smin), tmax = sort2f(g_smax);
    float range = tmax - tmin;
    float scale = (range > 0.f) ? (float)(NB - 1) / range : 0.f;
    int b = bucket_of(g_t[i], tmin, scale);
    g_b[i] = b;
    atomicAdd(&g_hist[b], 1);
}

// ---- 2b: exclusive scan of 4096-bucket hist (int4 + shfl, 2 syncs) ------
__global__ void __launch_bounds__(1024) hscan_k() {
    __shared__ int wsum[32], wscan[32];
    int tid = threadIdx.x;
    int lane = tid & 31, w = tid >> 5;
    int4 h = ((const int4*)g_hist)[tid];
    int s = h.x + h.y + h.z + h.w;
    int incl = s;
    #pragma unroll
    for (int off = 1; off < 32; off <<= 1) {
        int n = __shfl_up_sync(0xffffffffu, incl, off);
        if (lane >= off) incl += n;
    }
    if (lane == 31) wsum[w] = incl;
    __syncthreads();
    if (w == 0) {
        int t2 = wsum[lane];
        int i2 = t2;
        #pragma unroll
        for (int off = 1; off < 32; off <<= 1) {
            int n = __shfl_up_sync(0xffffffffu, i2, off);
            if (lane >= off) i2 += n;
        }
        wscan[lane] = i2 - t2;   // exclusive warp base
    }
    __syncthreads();
    int base = wscan[w] + incl - s;   // exclusive offset for this thread
    int4 o;
    o.x = base;
    o.y = base + h.x;
    o.z = base + h.x + h.y;
    o.w = base + h.x + h.y + h.z;
    ((int4*)g_cum)[tid] = o;
    if (tid == 0) g_cum[NB] = NR;
}

// ---- 2c: scatter elements into bucket-grouped arrays --------------------
__global__ void __launch_bounds__(128) place_k() {
    int i = blockIdx.x * 128 + threadIdx.x;
    int b = g_b[i];
    int pos = g_cum[b] + atomicAdd(&g_bcnt[b], 1);
    g_pkey[pos] = g_s[i];
    g_pid[pos]  = i;
}

// ---- 2d: exact rank + threshold rank + weights + (p,q) pair -------------
__global__ void __launch_bounds__(128) rank_k() {
    int i = blockIdx.x * 128 + threadIdx.x;
    unsigned si = g_s[i];
    int b = g_b[i];
    int lo = g_cum[b], hi = g_cum[b + 1];
    int r = lo;
    for (int p = lo; p < hi; p++) {
        unsigned sj = g_pkey[p];
        int ij = g_pid[p];
        r += (sj < si) || (sj == si && ij < i);
    }
    float T = sort2f(g_smax);
    float t = g_t[i];
    g_idx[r] = i;
    g_w1[r] = expf(t - T);
    g_w2[r] = expf(0.01f * (t - T));

    float c = g_ssrc[i];
    double gamma = exp(-0.99 * ((double)c + (double)T));
    if (gamma <= 1.0) { g_pf[i] = 1.f; g_qf[i] = (float)gamma; }
    else             { g_pf[i] = (float)(1.0 / gamma); g_qf[i] = 1.f; }

    float thr = -c;
    unsigned sthr = f2sort(thr);
    float tmin = sort2f(g_smin), tmax = sort2f(g_smax);
    float range = tmax - tmin;
    float scale = (range > 0.f) ? (float)(NB - 1) / range : 0.f;
    int bb = bucket_of(thr, tmin, scale);
    int kq = g_cum[bb];
    int hi2 = g_cum[bb + 1];
    for (int p = g_cum[bb]; p < hi2; p++) kq += (g_pkey[p] < sthr);
    g_kq[i] = kq;
}

// ---- 3: v = x @ Wv^T + bv, mma.sync bf16 split, BM=32 BN=64 BK=32 -------
// grid (NR/32, 2) = 512 blocks, 256 threads = 8 warps as 2(m) x 4(n).
#define ASTR 40   // bf16 row stride in smem (conflict-free)
#define ATILE (32 * ASTR)
#define BTILE (64 * ASTR)
__global__ void __launch_bounds__(256) gemm_v_k(const float* __restrict__ bv) {
    __shared__ __nv_bfloat16 Ah[2 * ATILE], Al[2 * ATILE];
    __shared__ __nv_bfloat16 Bh[2 * BTILE], Bl[2 * BTILE];
    int tid = threadIdx.x;
    int wid = tid >> 5, lane = tid & 31;
    int warp_m = wid >> 2, warp_n = wid & 3;    // 2 x 4 warps
    int grp = lane >> 2, qid = lane & 3;
    int i0 = blockIdx.x * 32;
    int n0 = blockIdx.y * 64;

    const __nv_bfloat16* xh = (const __nv_bfloat16*)g_xh2;
    const __nv_bfloat16* xl = (const __nv_bfloat16*)g_xl2;

    int lrow = tid >> 2, lcol = (tid & 3) * 8;          // lrow 0..63
    long aoff = (long)(i0 + lrow) * DIMK + lcol;        // valid when lrow < 32
    long boff = (long)(n0 + lrow) * DIMK + lcol;
    int sidx = lrow * ASTR + lcol;
    bool doA = (tid < 128);

    float acc[2][4];
    #pragma unroll
    for (int nt = 0; nt < 2; nt++)
        #pragma unroll
        for (int q = 0; q < 4; q++) acc[nt][q] = 0.f;

    if (doA) {
        cpasync16(&Ah[sidx], &xh[aoff]);
        cpasync16(&Al[sidx], &xl[aoff]);
    }
    cpasync16(&Bh[sidx], &g_wh[boff]);
    cpasync16(&Bl[sidx], &g_wl[boff]);
    asm volatile("cp.async.commit_group;\n");

    int buf = 0;
    for (int it = 0; it < DIMK / 32; it++) {
        if (it + 1 < DIMK / 32) {
            int nbA = (buf ^ 1) * ATILE;
            int nbB = (buf ^ 1) * BTILE;
            int k0 = (it + 1) * 32;
            if (doA) {
                cpasync16(&Ah[nbA + sidx], &xh[aoff + k0]);
                cpasync16(&Al[nbA + sidx], &xl[aoff + k0]);
            }
            cpasync16(&Bh[nbB + sidx], &g_wh[boff + k0]);
            cpasync16(&Bl[nbB + sidx], &g_wl[boff + k0]);
            asm volatile("cp.async.commit_group;\n");
            asm volatile("cp.async.wait_group 1;\n");
        } else {
            asm volatile("cp.async.wait_group 0;\n");
        }
        __syncthreads();
        int cbA = buf * ATILE;
        int cbB = buf * BTILE;
        #pragma unroll
        for (int kk = 0; kk < 32; kk += 16) {
            unsigned ah[4], al[4];
            int r0 = warp_m * 16 + grp;
            int cA = cbA + kk + qid * 2;
            ah[0] = *(unsigned*)&Ah[r0 * ASTR + cA];
            ah[1] = *(unsigned*)&Ah[(r0 + 8) * ASTR + cA];
            ah[2] = *(unsigned*)&Ah[r0 * ASTR + cA + 8];
            ah[3] = *(unsigned*)&Ah[(r0 + 8) * ASTR + cA + 8];
            al[0] = *(unsigned*)&Al[r0 * ASTR + cA];
            al[1] = *(unsigned*)&Al[(r0 + 8) * ASTR + cA];
            al[2] = *(unsigned*)&Al[r0 * ASTR + cA + 8];
            al[3] = *(unsigned*)&Al[(r0 + 8) * ASTR + cA + 8];
            int cB = cbB + kk + qid * 2;
            #pragma unroll
            for (int nt = 0; nt < 2; nt++) {
                int n = warp_n * 16 + nt * 8 + grp;
                unsigned bh[2], bl[2];
                bh[0] = *(unsigned*)&Bh[n * ASTR + cB];
                bh[1] = *(unsigned*)&Bh[n * ASTR + cB + 8];
                bl[0] = *(unsigned*)&Bl[n * ASTR + cB];
                bl[1] = *(unsigned*)&Bl[n * ASTR + cB + 8];
                mma16816(acc[nt], ah, bh);
                mma16816(acc[nt], ah, bl);
                mma16816(acc[nt], al, bh);
            }
        }
        __syncthreads();
        buf ^= 1;
    }
    #pragma unroll
    for (int nt = 0; nt < 2; nt++) {
        int col = n0 + warp_n * 16 + nt * 8 + qid * 2;
        float2 bb = *(const float2*)&bv[col];
        int row0 = i0 + warp_m * 16 + grp;
        float2 o0 = { acc[nt][0] + bb.x, acc[nt][1] + bb.y };
        float2 o1 = { acc[nt][2] + bb.x, acc[nt][3] + bb.y };
        *(float2*)&g_v[(long)row0 * DVC + col] = o0;
        *(float2*)&g_v[(long)(row0 + 8) * DVC + col] = o1;
    }
}

// ---- 4a: per-chunk local exclusive prefixes (fp32) + chunk totals -------
__global__ void __launch_bounds__(160) scan1_k() {
    int c = blockIdx.x, d = threadIdx.x;
    if (d > 128) return;
    float a1 = 0.f, a2 = 0.f;
    int k0 = c * CHS;
    #pragma unroll 4
    for (int e = 0; e < CHS; e++) {
        int k = k0 + e;
        float vv = (d < 128) ? g_v[g_idx[k] * DVC + d] : 1.0f;
        g_A1[k * STR + d] = a1;
        g_A2[k * STR + d] = a2;
        a1 = fmaf(g_w1[k], vv, a1);
        a2 = fmaf(g_w2[k], vv, a2);
    }
    g_cT1[c * STR + d] = (double)a1;
    g_cT2[c * STR + d] = (double)a2;
}

// ---- 4b: scan of chunk totals -> float suffix/prefix tables -------------
__global__ void __launch_bounds__(NCH) scan2_k() {
    __shared__ double s1[NCH], s2[NCH];
    int d = blockIdx.x, c = threadIdx.x;
    double v1 = g_cT1[c * STR + d], v2 = g_cT2[c * STR + d];
    s1[c] = v1; s2[c] = v2;
    __syncthreads();
    for (int off = 1; off < NCH; off <<= 1) {
        double a = (c >= off) ? s1[c - off] : 0.0;
        double b = (c >= off) ? s2[c - off] : 0.0;
        __syncthreads();
        s1[c] += a; s2[c] += b;
        __syncthreads();
    }
    double tot1 = s1[NCH - 1], tot2 = s2[NCH - 1];
    g_S1f[c * STR + d] = (float)(tot1 - (s1[c] - v1));  // suffix incl chunk c
    g_P2f[c * STR + d] = (float)(s2[c] - v2);           // prefix excl chunk c
    if (c == 0) {
        g_S1f[NCH * STR + d] = 0.f;
        g_P2f[NCH * STR + d] = (float)tot2;
    }
}

// ---- 5: per-row combine, pure fp32 --------------------------------------
__global__ void __launch_bounds__(128) final_k(float* __restrict__ out) {
    int d = threadIdx.x;
    int lane = d & 31;
    #pragma unroll
    for (int rr = 0; rr < 4; rr++) {
        int i = blockIdx.x * 4 + rr;
        int k = g_kq[i];
        float p = g_pf[i], q = g_qf[i];
        float suf, pre, sufZ, preZ;
        if (k < NR) {
            int ch = k / CHS;
            long cb = (long)ch * STR;
            long kb = (long)k * STR;
            suf  = g_S1f[cb + d]   - g_A1[kb + d];
            pre  = g_P2f[cb + d]   + g_A2[kb + d];
            sufZ = g_S1f[cb + 128] - g_A1[kb + 128];
            preZ = g_P2f[cb + 128] + g_A2[kb + 128];
        } else {
            long cb = (long)NCH * STR;
            suf = 0.f;  pre = g_P2f[cb + d];
            sufZ = 0.f; preZ = g_P2f[cb + 128];
        }
        float num = suf * p + pre * q;
        float den = sufZ * p + preZ * q;
        float inv;
        if (lane == 0) inv = 1.f / den;
        inv = __shfl_sync(0xffffffffu, inv, 0);
        out[i * DVC + d] = num * inv;
    }
}

// ---------------- launch --------------------------------------------------
extern "C" void kernel_launch(void* const* d_in, const int* in_sizes, int n_in,
                              void* d_out, int out_size) {
    const float* x  = (const float*)d_in[0];
    const float* W  = (const float*)d_in[1];
    const float* b  = (const float*)d_in[2];
    const float* Wv = (const float*)d_in[3];
    const float* bv = (const float*)d_in[4];
    const float* a  = (const float*)d_in[5];
    float* out = (float*)d_out;

    static cudaStream_t s2 = nullptr;
    static cudaEvent_t evFork = nullptr, evJoin = nullptr;
    if (!s2) {
        cudaStreamCreateWithFlags(&s2, cudaStreamNonBlocking);
        cudaEventCreateWithFlags(&evFork, cudaEventDisableTiming);
        cudaEventCreateWithFlags(&evJoin, cudaEventDisableTiming);
    }

    prep_k<<<32, 512>>>(W, b, a, Wv);
    s_k<<<NR / 8, 256>>>(x);

    // fork: bucket/rank chain (latency-bound) runs parallel to GEMM
    cudaEventRecord(evFork, 0);
    cudaStreamWaitEvent(s2, evFork, 0);
    hist_k<<<NR / 128, 128, 0, s2>>>();
    hscan_k<<<1, 1024, 0, s2>>>();
    place_k<<<NR / 128, 128, 0, s2>>>();
    rank_k<<<NR / 128, 128, 0, s2>>>();
    cudaEventRecord(evJoin, s2);

    dim3 ggrid(NR / 32, 2);
    gemm_v_k<<<ggrid, 256>>>(bv);

    // join
    cudaStreamWaitEvent(0, evJoin, 0);
    scan1_k<<<NCH, 160>>>();
    scan2_k<<<129, NCH>>>();
    final_k<<<NR / 4, 128>>>(out);
}

// round 14
// speedup vs baseline: 1.4119x; 1.1008x over previous
#include <cuda_runtime.h>
#include <cuda_bf16.h>
#include <math.h>
#include <stdint.h>

#define NR   8192
#define DIMK 512
#define DKC  128
#define DVC  128
#define NCH  256
#define CHS  32      // NCH*CHS == NR
#define NB   4096    // rank buckets
#define STR  132     // padded column stride (129 used: 128 v-cols + 1 weight col)

// ---------------- scratch (device globals; no allocation) ----------------
__device__ float          g_u1[DIMK], g_u2[DIMK];
__device__ float          g_d1, g_d2;
__device__ __nv_bfloat16  g_wh[DVC * DIMK], g_wl[DVC * DIMK];
__device__ float          g_v[NR * DVC];
__device__ float          g_ssrc[NR];
__device__ float          g_t[NR];
__device__ unsigned       g_s[NR];          // sortable u32 of t
__device__ int            g_b[NR];          // bucket of t
__device__ unsigned       g_smin, g_smax;   // sortable min/max of t
__device__ int            g_hist[NB], g_bcnt[NB], g_cum[NB + 1];
__device__ unsigned       g_pkey[NR];       // bucket-grouped keys
__device__ int            g_pid[NR];        // bucket-grouped indices
__device__ int            g_idx[NR];        // sorted order -> original index
__device__ int            g_kq[NR];         // per-row threshold rank
__device__ float          g_pf[NR], g_qf[NR];  // per-row (p,q) mixing pair
__device__ float          g_w1[NR], g_w2[NR];
__device__ float          g_A1[NR * STR];   // per-chunk local exclusive prefix, w1*v
__device__ float          g_A2[NR * STR];   // per-chunk local exclusive prefix, w2*v
__device__ double         g_cT1[NCH * STR], g_cT2[NCH * STR];
__device__ float          g_S1f[(NCH + 1) * STR];  // suffix incl chunk (float)
__device__ float          g_P2f[(NCH + 1) * STR];  // prefix excl chunk (float)

__device__ __forceinline__ unsigned f2sort(float f) {
    unsigned u = __float_as_uint(f);
    return (u & 0x80000000u) ? ~u : (u | 0x80000000u);
}
__device__ __forceinline__ float sort2f(unsigned s) {
    unsigned u = (s & 0x80000000u) ? (s & 0x7FFFFFFFu) : ~s;
    return __uint_as_float(u);
}
__device__ __forceinline__ int bucket_of(float t, float tmin, float scale) {
    int b = (int)((t - tmin) * scale);
    if (b < 0) b = 0;
    if (b > NB - 1) b = NB - 1;
    return b;
}
__device__ __forceinline__ void mma16816(float* c, const unsigned* a, const unsigned* b) {
    asm volatile(
        "mma.sync.aligned.m16n8k16.row.col.f32.bf16.bf16.f32 "
        "{%0,%1,%2,%3}, {%4,%5,%6,%7}, {%8,%9}, {%0,%1,%2,%3};\n"
        : "+f"(c[0]), "+f"(c[1]), "+f"(c[2]), "+f"(c[3])
        : "r"(a[0]), "r"(a[1]), "r"(a[2]), "r"(a[3]), "r"(b[0]), "r"(b[1]));
}
__device__ __forceinline__ void cpasync16(void* smem, const void* gmem) {
    unsigned sa = (unsigned)__cvta_generic_to_shared(smem);
    asm volatile("cp.async.cg.shared.global [%0], [%1], 16;\n" :: "r"(sa), "l"(gmem));
}

// ---------------- 0: clear hist + fold a into W + convert Wv -------------
__global__ void __launch_bounds__(512) prep_k(const float* __restrict__ W,
                                              const float* __restrict__ b,
                                              const float* __restrict__ a,
                                              const float* __restrict__ Wv) {
    int gi = blockIdx.x * 512 + threadIdx.x;   // 0..16383
    if (gi < NB) { g_hist[gi] = 0; g_bcnt[gi] = 0; }
    if (gi == 0) { g_smin = 0xFFFFFFFFu; g_smax = 0u; }
    int e0 = gi * 4;
    #pragma unroll
    for (int j = 0; j < 4; j++) {
        float w = Wv[e0 + j];
        __nv_bfloat16 h = __float2bfloat16_rn(w);
        __nv_bfloat16 l = __float2bfloat16_rn(w - __bfloat162float(h));
        g_wh[e0 + j] = h;
        g_wl[e0 + j] = l;
    }
    if (blockIdx.x == 0) {
        int j = threadIdx.x;  // 0..511
        float u1 = 0.f, u2 = 0.f;
        #pragma unroll 8
        for (int k = 0; k < DKC; k++) {
            float w = W[k * DIMK + j];
            u1 += w * a[k];
            u2 += w * a[DKC + k];
        }
        g_u1[j] = u1;
        g_u2[j] = u2;
        if (j < 2) {
            float d = 0.f;
            const float* av = a + (j ? DKC : 0);
            for (int k = 0; k < DKC; k++) d += b[k] * av[k];
            if (j == 0) g_d1 = d; else g_d2 = d;
        }
    }
}

// ---- 1: s_src, t, sortable key, min/max (no conversion — pure matvec) ---
__global__ void __launch_bounds__(256) s_k(const float* __restrict__ x) {
    __shared__ unsigned wmin[8], wmax[8];
    int warp = threadIdx.x >> 5, lane = threadIdx.x & 31;
    int row = blockIdx.x * 8 + warp;
    const float4* xr = (const float4*)(x + row * DIMK);
    const float4* u1v = (const float4*)g_u1;
    const float4* u2v = (const float4*)g_u2;
    float a1 = 0.f, a2 = 0.f;
    #pragma unroll
    for (int m = lane; m < DIMK / 4; m += 32) {
        float4 xv = xr[m];
        float4 w1 = u1v[m];
        float4 w2 = u2v[m];
        a1 += xv.x * w1.x + xv.y * w1.y + xv.z * w1.z + xv.w * w1.w;
        a2 += xv.x * w2.x + xv.y * w2.y + xv.z * w2.z + xv.w * w2.w;
    }
    #pragma unroll
    for (int off = 16; off > 0; off >>= 1) {
        a1 += __shfl_down_sync(0xffffffffu, a1, off);
        a2 += __shfl_down_sync(0xffffffffu, a2, off);
    }
    if (lane == 0) {
        float t = a2 + g_d2;
        g_ssrc[row] = a1 + g_d1;
        g_t[row] = t;
        unsigned s = f2sort(t);
        g_s[row] = s;
        wmin[warp] = s; wmax[warp] = s;
    }
    __syncthreads();
    if (threadIdx.x == 0) {
        unsigned mn = wmin[0], mx = wmax[0];
        #pragma unroll
        for (int w = 1; w < 8; w++) {
            mn = min(mn, wmin[w]);
            mx = max(mx, wmax[w]);
        }
        atomicMin(&g_smin, mn);
        atomicMax(&g_smax, mx);
    }
}

// ---- 2a: histogram of buckets -------------------------------------------
__global__ void __launch_bounds__(128) hist_k() {
    int i = blockIdx.x * 128 + threadIdx.x;
    float tmin = sort2f(g_smin), tmax = sort2f(g_smax);
    float range = tmax - tmin;
    float scale = (range > 0.f) ? (float)(NB - 1) / range : 0.f;
    int b = bucket_of(g_t[i], tmin, scale);
    g_b[i] = b;
    atomicAdd(&g_hist[b], 1);
}

// ---- 2b: exclusive scan of 4096-bucket hist (int4 + shfl, 2 syncs) ------
__global__ void __launch_bounds__(1024) hscan_k() {
    __shared__ int wsum[32], wscan[32];
    int tid = threadIdx.x;
    int lane = tid & 31, w = tid >> 5;
    int4 h = ((const int4*)g_hist)[tid];
    int s = h.x + h.y + h.z + h.w;
    int incl = s;
    #pragma unroll
    for (int off = 1; off < 32; off <<= 1) {
        int n = __shfl_up_sync(0xffffffffu, incl, off);
        if (lane >= off) incl += n;
    }
    if (lane == 31) wsum[w] = incl;
    __syncthreads();
    if (w == 0) {
        int t2 = wsum[lane];
        int i2 = t2;
        #pragma unroll
        for (int off = 1; off < 32; off <<= 1) {
            int n = __shfl_up_sync(0xffffffffu, i2, off);
            if (lane >= off) i2 += n;
        }
        wscan[lane] = i2 - t2;   // exclusive warp base
    }
    __syncthreads();
    int base = wscan[w] + incl - s;   // exclusive offset for this thread
    int4 o;
    o.x = base;
    o.y = base + h.x;
    o.z = base + h.x + h.y;
    o.w = base + h.x + h.y + h.z;
    ((int4*)g_cum)[tid] = o;
    if (tid == 0) g_cum[NB] = NR;
}

// ---- 2c: scatter elements into bucket-grouped arrays --------------------
__global__ void __launch_bounds__(128) place_k() {
    int i = blockIdx.x * 128 + threadIdx.x;
    int b = g_b[i];
    int pos = g_cum[b] + atomicAdd(&g_bcnt[b], 1);
    g_pkey[pos] = g_s[i];
    g_pid[pos]  = i;
}

// ---- 2d: exact rank + threshold rank + weights + (p,q) pair -------------
__global__ void __launch_bounds__(128) rank_k() {
    int i = blockIdx.x * 128 + threadIdx.x;
    unsigned si = g_s[i];
    int b = g_b[i];
    int lo = g_cum[b], hi = g_cum[b + 1];
    int r = lo;
    for (int p = lo; p < hi; p++) {
        unsigned sj = g_pkey[p];
        int ij = g_pid[p];
        r += (sj < si) || (sj == si && ij < i);
    }
    float T = sort2f(g_smax);
    float t = g_t[i];
    g_idx[r] = i;
    g_w1[r] = expf(t - T);
    g_w2[r] = expf(0.01f * (t - T));

    float c = g_ssrc[i];
    double gamma = exp(-0.99 * ((double)c + (double)T));
    if (gamma <= 1.0) { g_pf[i] = 1.f; g_qf[i] = (float)gamma; }
    else             { g_pf[i] = (float)(1.0 / gamma); g_qf[i] = 1.f; }

    float thr = -c;
    unsigned sthr = f2sort(thr);
    float tmin = sort2f(g_smin), tmax = sort2f(g_smax);
    float range = tmax - tmin;
    float scale = (range > 0.f) ? (float)(NB - 1) / range : 0.f;
    int bb = bucket_of(thr, tmin, scale);
    int kq = g_cum[bb];
    int hi2 = g_cum[bb + 1];
    for (int p = g_cum[bb]; p < hi2; p++) kq += (g_pkey[p] < sthr);
    g_kq[i] = kq;
}

// ---- 3: v = x @ Wv^T + bv. x read DIRECTLY (fp32 LDG -> convert -> STS).
// BM=32, BN=64, BK=32, grid (NR/32, 2), 256 thr = 8 warps as 2(m) x 4(n).
#define ASTR 40   // bf16 row stride in smem (conflict-free)
#define BTILE (64 * ASTR)
__global__ void __launch_bounds__(256) gemm_v_k(const float* __restrict__ x,
                                                const float* __restrict__ bv) {
    __shared__ __nv_bfloat16 Ah[32 * ASTR], Al[32 * ASTR];
    __shared__ __nv_bfloat16 Bh[2 * BTILE], Bl[2 * BTILE];
    int tid = threadIdx.x;
    int wid = tid >> 5, lane = tid & 31;
    int warp_m = wid >> 2, warp_n = wid & 3;    // 2 x 4 warps
    int grp = lane >> 2, qid = lane & 3;
    int i0 = blockIdx.x * 32;
    int n0 = blockIdx.y * 64;

    // A: fp32 direct load. row = tid>>3 (0..31), col = (tid&7)*4
    int arow = tid >> 3, acol = (tid & 7) * 4;
    const float* xptr = x + (long)(i0 + arow) * DIMK + acol;
    int asidx = arow * ASTR + acol;

    // B: bf16 cp.async. row = tid>>2 (0..63), col = (tid&3)*8
    int brow = tid >> 2, bcol = (tid & 3) * 8;
    long boff = (long)(n0 + brow) * DIMK + bcol;
    int bsidx = brow * ASTR + bcol;

    float acc[2][4];
    #pragma unroll
    for (int nt = 0; nt < 2; nt++)
        #pragma unroll
        for (int q = 0; q < 4; q++) acc[nt][q] = 0.f;

    float4 xreg = *(const float4*)xptr;          // k-tile 0
    cpasync16(&Bh[bsidx], &g_wh[boff]);
    cpasync16(&Bl[bsidx], &g_wl[boff]);
    asm volatile("cp.async.commit_group;\n");

    int buf = 0;
    #pragma unroll 1
    for (int it = 0; it < DIMK / 32; it++) {
        float4 xnext;
        if (it + 1 < DIMK / 32) {
            int k0 = (it + 1) * 32;
            xnext = *(const float4*)(xptr + k0);
            int nb = (buf ^ 1) * BTILE;
            cpasync16(&Bh[nb + bsidx], &g_wh[boff + k0]);
            cpasync16(&Bl[nb + bsidx], &g_wl[boff + k0]);
            asm volatile("cp.async.commit_group;\n");
        }
        // convert this k-tile of A into smem (same split math as before)
        {
            __nv_bfloat162 h0 = __floats2bfloat162_rn(xreg.x, xreg.y);
            __nv_bfloat162 h1 = __floats2bfloat162_rn(xreg.z, xreg.w);
            __nv_bfloat162 l0 = __floats2bfloat162_rn(xreg.x - __bfloat162float(h0.x),
                                                      xreg.y - __bfloat162float(h0.y));
            __nv_bfloat162 l1 = __floats2bfloat162_rn(xreg.z - __bfloat162float(h1.x),
                                                      xreg.w - __bfloat162float(h1.y));
            *(__nv_bfloat162*)&Ah[asidx]     = h0;
            *(__nv_bfloat162*)&Ah[asidx + 2] = h1;
            *(__nv_bfloat162*)&Al[asidx]     = l0;
            *(__nv_bfloat162*)&Al[asidx + 2] = l1;
        }
        if (it + 1 < DIMK / 32) asm volatile("cp.async.wait_group 1;\n");
        else                    asm volatile("cp.async.wait_group 0;\n");
        __syncthreads();
        int cbB = buf * BTILE;
        #pragma unroll
        for (int kk = 0; kk < 32; kk += 16) {
            unsigned ah[4], al[4];
            int r0 = warp_m * 16 + grp;
            int cA = kk + qid * 2;
            ah[0] = *(unsigned*)&Ah[r0 * ASTR + cA];
            ah[1] = *(unsigned*)&Ah[(r0 + 8) * ASTR + cA];
            ah[2] = *(unsigned*)&Ah[r0 * ASTR + cA + 8];
            ah[3] = *(unsigned*)&Ah[(r0 + 8) * ASTR + cA + 8];
            al[0] = *(unsigned*)&Al[r0 * ASTR + cA];
            al[1] = *(unsigned*)&Al[(r0 + 8) * ASTR + cA];
            al[2] = *(unsigned*)&Al[r0 * ASTR + cA + 8];
            al[3] = *(unsigned*)&Al[(r0 + 8) * ASTR + cA + 8];
            int cB = cbB + kk + qid * 2;
            #pragma unroll
            for (int nt = 0; nt < 2; nt++) {
                int n = warp_n * 16 + nt * 8 + grp;
                unsigned bh[2], bl[2];
                bh[0] = *(unsigned*)&Bh[n * ASTR + cB];
                bh[1] = *(unsigned*)&Bh[n * ASTR + cB + 8];
                bl[0] = *(unsigned*)&Bl[n * ASTR + cB];
                bl[1] = *(unsigned*)&Bl[n * ASTR + cB + 8];
                mma16816(acc[nt], ah, bh);
                mma16816(acc[nt], ah, bl);
                mma16816(acc[nt], al, bh);
            }
        }
        __syncthreads();
        xreg = xnext;
        buf ^= 1;
    }
    #pragma unroll
    for (int nt = 0; nt < 2; nt++) {
        int col = n0 + warp_n * 16 + nt * 8 + qid * 2;
        float2 bb = *(const float2*)&bv[col];
        int row0 = i0 + warp_m * 16 + grp;
        float2 o0 = { acc[nt][0] + bb.x, acc[nt][1] + bb.y };
        float2 o1 = { acc[nt][2] + bb.x, acc[nt][3] + bb.y };
        *(float2*)&g_v[(long)row0 * DVC + col] = o0;
        *(float2*)&g_v[(long)(row0 + 8) * DVC + col] = o1;
    }
}

// ---- 4a: per-chunk local exclusive prefixes (fp32) + chunk totals -------
__global__ void __launch_bounds__(160) scan1_k() {
    int c = blockIdx.x, d = threadIdx.x;
    if (d > 128) return;
    float a1 = 0.f, a2 = 0.f;
    int k0 = c * CHS;
    #pragma unroll 4
    for (int e = 0; e < CHS; e++) {
        int k = k0 + e;
        float vv = (d < 128) ? g_v[g_idx[k] * DVC + d] : 1.0f;
        g_A1[k * STR + d] = a1;
        g_A2[k * STR + d] = a2;
        a1 = fmaf(g_w1[k], vv, a1);
        a2 = fmaf(g_w2[k], vv, a2);
    }
    g_cT1[c * STR + d] = (double)a1;
    g_cT2[c * STR + d] = (double)a2;
}

// ---- 4b: scan of chunk totals -> float suffix/prefix tables -------------
__global__ void __launch_bounds__(NCH) scan2_k() {
    __shared__ double s1[NCH], s2[NCH];
    int d = blockIdx.x, c = threadIdx.x;
    double v1 = g_cT1[c * STR + d], v2 = g_cT2[c * STR + d];
    s1[c] = v1; s2[c] = v2;
    __syncthreads();
    for (int off = 1; off < NCH; off <<= 1) {
        double a = (c >= off) ? s1[c - off] : 0.0;
        double b = (c >= off) ? s2[c - off] : 0.0;
        __syncthreads();
        s1[c] += a; s2[c] += b;
        __syncthreads();
    }
    double tot1 = s1[NCH - 1], tot2 = s2[NCH - 1];
    g_S1f[c * STR + d] = (float)(tot1 - (s1[c] - v1));  // suffix incl chunk c
    g_P2f[c * STR + d] = (float)(s2[c] - v2);           // prefix excl chunk c
    if (c == 0) {
        g_S1f[NCH * STR + d] = 0.f;
        g_P2f[NCH * STR + d] = (float)tot2;
    }
}

// ---- 5: per-row combine, pure fp32 --------------------------------------
__global__ void __launch_bounds__(128) final_k(float* __restrict__ out) {
    int d = threadIdx.x;
    int lane = d & 31;
    #pragma unroll
    for (int rr = 0; rr < 4; rr++) {
        int i = blockIdx.x * 4 + rr;
        int k = g_kq[i];
        float p = g_pf[i], q = g_qf[i];
        float suf, pre, sufZ, preZ;
        if (k < NR) {
            int ch = k / CHS;
            long cb = (long)ch * STR;
            long kb = (long)k * STR;
            suf  = g_S1f[cb + d]   - g_A1[kb + d];
            pre  = g_P2f[cb + d]   + g_A2[kb + d];
            sufZ = g_S1f[cb + 128] - g_A1[kb + 128];
            preZ = g_P2f[cb + 128] + g_A2[kb + 128];
        } else {
            long cb = (long)NCH * STR;
            suf = 0.f;  pre = g_P2f[cb + d];
            sufZ = 0.f; preZ = g_P2f[cb + 128];
        }
        float num = suf * p + pre * q;
        float den = sufZ * p + preZ * q;
        float inv;
        if (lane == 0) inv = 1.f / den;
        inv = __shfl_sync(0xffffffffu, inv, 0);
        out[i * DVC + d] = num * inv;
    }
}

// ---------------- launch --------------------------------------------------
extern "C" void kernel_launch(void* const* d_in, const int* in_sizes, int n_in,
                              void* d_out, int out_size) {
    const float* x  = (const float*)d_in[0];
    const float* W  = (const float*)d_in[1];
    const float* b  = (const float*)d_in[2];
    const float* Wv = (const float*)d_in[3];
    const float* bv = (const float*)d_in[4];
    const float* a  = (const float*)d_in[5];
    float* out = (float*)d_out;

    static cudaStream_t s2 = nullptr;
    static cudaEvent_t evPrep = nullptr, evJoin = nullptr;
    if (!s2) {
        cudaStreamCreateWithFlags(&s2, cudaStreamNonBlocking);
        cudaEventCreateWithFlags(&evPrep, cudaEventDisableTiming);
        cudaEventCreateWithFlags(&evJoin, cudaEventDisableTiming);
    }

    prep_k<<<32, 512>>>(W, b, a, Wv);

    // fork: the ENTIRE scalar side (s_k + bucket chain) runs parallel to GEMM
    cudaEventRecord(evPrep, 0);
    cudaStreamWaitEvent(s2, evPrep, 0);
    s_k<<<NR / 8, 256, 0, s2>>>(x);
    hist_k<<<NR / 128, 128, 0, s2>>>();
    hscan_k<<<1, 1024, 0, s2>>>();
    place_k<<<NR / 128, 128, 0, s2>>>();
    rank_k<<<NR / 128, 128, 0, s2>>>();
    cudaEventRecord(evJoin, s2);

    // GEMM depends only on prep (reads x directly, converts in-kernel)
    dim3 ggrid(NR / 32, 2);
    gemm_v_k<<<ggrid, 256>>>(x, bv);

    // join
    cudaStreamWaitEvent(0, evJoin, 0);
    scan1_k<<<NCH, 160>>>();
    scan2_k<<<129, NCH>>>();
    final_k<<<NR / 4, 128>>>(out);
}